// round 13
// baseline (speedup 1.0000x reference)
#include <cuda_runtime.h>
#include <cstdint>

#define B_  16
#define C_  256
#define H_  64
#define W_  64
#define K_  31
#define PAD_ 15
#define HW_ 4096
#define NIMG (B_ * C_)      // 4096 (b,c) images
#define NBLK 304            // persistent blocks (2 per SM on 152-SM GB300)

// dwconv: vertical-pair packed tile (R12-proven compute core)
#define PV_ROWS 62          // r = 0..61 ; pair (tile r, tile r+32)
#define PV_COLS 94          // 64 + 30 halo
#define PV_S    95          // f2 row stride (odd -> conflict-free LDS.64 across rows)
#define WROW    32          // padded weight row (f2 per kh); 16B-aligned rows
#define BUF_F2  (PV_ROWS * PV_S + K_ * WROW)   // 6882 float2 per buffer
#define DW_SMEM_BYTES (2 * BUF_F2 * 8)         // 110112 B (double-buffered)

// Scratch (allocation-free rule: __device__ globals)
__device__ float g_y[(size_t)B_ * C_ * HW_];
__device__ float g_pwT[C_ * C_];              // pwT[c][o] = pw[o][c]
__device__ float g_psum[C_ * B_];
__device__ float g_psumsq[C_ * B_];
__device__ float g_scale[C_];
__device__ float g_bias[C_];

// Packed f32x2 FMA (Blackwell sm_103a; only reachable via PTX)
#define FMA2(d, a, b) \
    asm("fma.rn.f32x2 %0, %1, %2, %0;" : "+l"(d) : "l"(a), "l"(b))

// 4-byte cp.async with zfill (src_bytes = 4 copies, 0 zero-fills)
#define CP_ASYNC4(dst_saddr, src_ptr, src_bytes) \
    asm volatile("cp.async.ca.shared.global [%0], [%1], 4, %2;" \
                 :: "r"(dst_saddr), "l"(src_ptr), "r"(src_bytes) : "memory")
#define CP_COMMIT()  asm volatile("cp.async.commit_group;" ::: "memory")
#define CP_WAIT0()   asm volatile("cp.async.wait_group 0;" ::: "memory")

union U2F { unsigned long long u; float2 f; };

// Bs mid-row gap mapping: word w -> w + 4*(w>=32)  (breaks 2-way bank conflict)
#define BS_COL(w) ((w) + (((w) >= 32) ? 4 : 0))

// ---------------------------------------------------------------------------
// Kernel 0: transpose pw (256x256) -> g_pwT
// ---------------------------------------------------------------------------
__global__ void transpose_kernel(const float* __restrict__ pw) {
    __shared__ float t[32][33];
    const int tx = threadIdx.x, ty = threadIdx.y;
    const int c0 = blockIdx.x * 32;
    const int o0 = blockIdx.y * 32;
    #pragma unroll
    for (int j = ty; j < 32; j += 8)
        t[j][tx] = pw[(o0 + j) * C_ + c0 + tx];
    __syncthreads();
    #pragma unroll
    for (int j = ty; j < 32; j += 8)
        g_pwT[(c0 + j) * C_ + o0 + tx] = t[tx][j];
}

// ---------------------------------------------------------------------------
// dwconv helpers
// ---------------------------------------------------------------------------
__device__ __forceinline__ void issue_image_loads(uint32_t sbuf,       // shared addr of buffer
                                                  const float* __restrict__ x,
                                                  const float* __restrict__ dw,
                                                  int img, int tid) {
    const int c = img & (C_ - 1);
    const int b = img >> 8;
    const float* xp = x + (size_t)(b * C_ + c) * HW_;

    // vertical-pair tile: element (r,cc) -> pair (x[r-15][cc-15], x[r+17][cc-15])
    for (int i = tid; i < PV_ROWS * PV_COLS; i += 128) {
        int r  = i / PV_COLS;
        int cc = i - r * PV_COLS;
        int gw = cc - PAD_;
        int gh0 = r - PAD_;
        int gh1 = r + 32 - PAD_;
        uint32_t dst = sbuf + (uint32_t)(r * PV_S + cc) * 8u;
        bool okw = (unsigned)gw < (unsigned)W_;
        bool ok0 = okw && (unsigned)gh0 < (unsigned)H_;
        bool ok1 = okw && (unsigned)gh1 < (unsigned)H_;
        const float* s0 = xp + (ok0 ? gh0 * W_ + gw : 0);
        const float* s1 = xp + (ok1 ? gh1 * W_ + gw : 0);
        CP_ASYNC4(dst,      s0, ok0 ? 4u : 0u);
        CP_ASYNC4(dst + 4u, s1, ok1 ? 4u : 0u);
    }
    // duplicated weights (w,w), rows padded to WROW
    const float* wp = dw + c * (K_ * K_);
    uint32_t wbase = sbuf + (uint32_t)(PV_ROWS * PV_S) * 8u;
    for (int i = tid; i < K_ * K_; i += 128) {
        int kh = i / K_, kw = i - kh * K_;
        uint32_t dst = wbase + (uint32_t)(kh * WROW + kw) * 8u;
        CP_ASYNC4(dst,      wp + i, 4u);
        CP_ASYNC4(dst + 4u, wp + i, 4u);
    }
    CP_COMMIT();
}

// R12-proven compute core on one buffered image
__device__ __forceinline__ void compute_image(const float2* __restrict__ pv,
                                              const float2* __restrict__ wsm2,
                                              float red[2][4],
                                              int img, int tid) {
    const int c = img & (C_ - 1);
    const int b = img >> 8;
    const int h  = tid & 31;
    const int w0 = (tid >> 5) << 4;

    unsigned long long acc2[16];
    #pragma unroll
    for (int j = 0; j < 16; ++j) acc2[j] = 0ULL;

    const unsigned long long* pvR =
        (const unsigned long long*)pv + (size_t)h * PV_S + w0;

    #pragma unroll 1
    for (int kh = 0; kh < K_; ++kh) {
        unsigned long long win[46];
        #pragma unroll
        for (int t = 0; t < 46; ++t) win[t] = pvR[t];

        const ulonglong2* wR2 = (const ulonglong2*)(wsm2 + kh * WROW);
        #pragma unroll
        for (int kwp = 0; kwp < 15; ++kwp) {
            ulonglong2 wq = wR2[kwp];
            #pragma unroll
            for (int j = 0; j < 16; ++j)
                FMA2(acc2[j], win[j + 2 * kwp], wq.x);
            #pragma unroll
            for (int j = 0; j < 16; ++j)
                FMA2(acc2[j], win[j + 2 * kwp + 1], wq.y);
        }
        {
            ulonglong2 wq = wR2[15];
            #pragma unroll
            for (int j = 0; j < 16; ++j)
                FMA2(acc2[j], win[j + 30], wq.x);
        }
        pvR += PV_S;
    }

    float* ypA = g_y + (size_t)(b * C_ + c) * HW_ + h * W_ + w0;
    float* ypB = ypA + 32 * W_;
    float s = 0.0f, s2 = 0.0f;
    float rowA[16], rowB[16];
    #pragma unroll
    for (int j = 0; j < 16; ++j) {
        U2F u; u.u = acc2[j];
        rowA[j] = u.f.x;
        rowB[j] = u.f.y;
        s  += u.f.x + u.f.y;
        s2  = fmaf(u.f.x, u.f.x, s2);
        s2  = fmaf(u.f.y, u.f.y, s2);
    }
    #pragma unroll
    for (int q = 0; q < 4; ++q) {
        *(float4*)(ypA + 4 * q) = make_float4(rowA[4*q], rowA[4*q+1], rowA[4*q+2], rowA[4*q+3]);
        *(float4*)(ypB + 4 * q) = make_float4(rowB[4*q], rowB[4*q+1], rowB[4*q+2], rowB[4*q+3]);
    }
    #pragma unroll
    for (int off = 16; off > 0; off >>= 1) {
        s  += __shfl_down_sync(0xffffffffu, s,  off);
        s2 += __shfl_down_sync(0xffffffffu, s2, off);
    }
    const int warp = tid >> 5;
    const int lane = tid & 31;
    if (lane == 0) { red[0][warp] = s; red[1][warp] = s2; }
    __syncthreads();
    if (tid == 0) {
        float ts = 0.0f, t2 = 0.0f;
        #pragma unroll
        for (int w = 0; w < 4; ++w) { ts += red[0][w]; t2 += red[1][w]; }
        g_psum[c * B_ + b]   = ts;
        g_psumsq[c * B_ + b] = t2;
    }
}

// ---------------------------------------------------------------------------
// Kernel 1: persistent double-buffered depthwise conv.
// Each block loops over images blk, blk+NBLK, ... ; next image's tile+weights
// prefetched via cp.async (4B + zfill) while current image computes.
// ---------------------------------------------------------------------------
__global__ void __launch_bounds__(128, 2)
dwconv_kernel(const float* __restrict__ x, const float* __restrict__ dw) {
    extern __shared__ float2 sm[];
    __shared__ float red[2][4];

    const int tid = threadIdx.x;
    const int blk = blockIdx.x;
    const int nimg = (NIMG - blk + NBLK - 1) / NBLK;
    if (nimg <= 0) return;

    float2* buf[2] = { sm, sm + BUF_F2 };
    uint32_t sbuf[2];
    sbuf[0] = (uint32_t)__cvta_generic_to_shared(buf[0]);
    sbuf[1] = (uint32_t)__cvta_generic_to_shared(buf[1]);

    // prologue: start loading image 0 into buffer 0
    issue_image_loads(sbuf[0], x, dw, blk, tid);

    #pragma unroll 1
    for (int t = 0; t < nimg; ++t) {
        const int img = blk + t * NBLK;
        const int cur = t & 1;

        CP_WAIT0();
        __syncthreads();      // buf[cur] fully loaded + everyone done with prior compute

        if (t + 1 < nimg)
            issue_image_loads(sbuf[cur ^ 1], x, dw, blk + (t + 1) * NBLK, tid);

        compute_image(buf[cur], buf[cur] + PV_ROWS * PV_S, red, img, tid);
    }
}

// ---------------------------------------------------------------------------
// Kernel 2: fold B partials per channel -> scale/bias  (deterministic)
// ---------------------------------------------------------------------------
__global__ void stats_kernel(const float* __restrict__ gamma,
                             const float* __restrict__ beta) {
    const int c = threadIdx.x;
    float s = 0.0f, s2 = 0.0f;
    #pragma unroll
    for (int b = 0; b < B_; ++b) {
        s  += g_psum[c * B_ + b];
        s2 += g_psumsq[c * B_ + b];
    }
    const float inv  = 1.0f / (float)(B_ * HW_);
    const float mean = s * inv;
    const float var  = s2 * inv - mean * mean;
    const float rstd = rsqrtf(var + 1e-5f);
    const float sc   = rstd * gamma[c];
    g_scale[c] = sc;
    g_bias[c]  = beta[c] - mean * sc;
}

// ---------------------------------------------------------------------------
// Kernel 3: fused normalize+ReLU+pointwise GEMM (R12-proven: full-M tile,
// coalesced A from g_pwT, register double-buffer, gapped Bs).
// ---------------------------------------------------------------------------
__global__ void __launch_bounds__(256, 2)
pw_kernel(float* __restrict__ out) {
    __shared__ float As[16][256];
    __shared__ float Bs[16][68];

    const int b   = blockIdx.y;
    const int hw0 = blockIdx.x * 64;
    const int tid = threadIdx.x;
    const int tm  = tid >> 3;
    const int tn  = tid & 7;
    const int lk  = tid >> 4;
    const int ln4 = (tid & 15) * 4;

    const int bsw = BS_COL(ln4);
    const int bA_col = BS_COL(tn * 8);
    const int bB_col = BS_COL(tn * 8 + 4);

    const float* yb = g_y + (size_t)b * C_ * HW_ + hw0;

    float acc[8][8];
    #pragma unroll
    for (int i = 0; i < 8; ++i)
        #pragma unroll
        for (int j = 0; j < 8; ++j) acc[i][j] = 0.0f;

    float4 a4[4], b4;
    #pragma unroll
    for (int p = 0; p < 4; ++p)
        a4[p] = *(const float4*)&g_pwT[lk * C_ + ln4 + 64 * p];
    b4 = *(const float4*)&yb[(size_t)lk * HW_ + ln4];

    for (int c0 = 0; c0 < C_; c0 += 16) {
        #pragma unroll
        for (int p = 0; p < 4; ++p)
            *(float4*)&As[lk][ln4 + 64 * p] = a4[p];
        {
            const int cc = c0 + lk;
            const float sc = g_scale[cc];
            const float bi = g_bias[cc];
            float4 r;
            r.x = fmaxf(fmaf(b4.x, sc, bi), 0.0f);
            r.y = fmaxf(fmaf(b4.y, sc, bi), 0.0f);
            r.z = fmaxf(fmaf(b4.z, sc, bi), 0.0f);
            r.w = fmaxf(fmaf(b4.w, sc, bi), 0.0f);
            *(float4*)&Bs[lk][bsw] = r;
        }
        __syncthreads();

        if (c0 + 16 < C_) {
            const int ck = c0 + 16 + lk;
            #pragma unroll
            for (int p = 0; p < 4; ++p)
                a4[p] = *(const float4*)&g_pwT[ck * C_ + ln4 + 64 * p];
            b4 = *(const float4*)&yb[(size_t)ck * HW_ + ln4];
        }

        #pragma unroll
        for (int kk = 0; kk < 16; ++kk) {
            float4 aA = *(const float4*)&As[kk][tm * 8];
            float4 aB = *(const float4*)&As[kk][tm * 8 + 4];
            float4 bA = *(const float4*)&Bs[kk][bA_col];
            float4 bB = *(const float4*)&Bs[kk][bB_col];
            const float a_[8] = {aA.x, aA.y, aA.z, aA.w, aB.x, aB.y, aB.z, aB.w};
            const float b_[8] = {bA.x, bA.y, bA.z, bA.w, bB.x, bB.y, bB.z, bB.w};
            #pragma unroll
            for (int i = 0; i < 8; ++i)
                #pragma unroll
                for (int j = 0; j < 8; ++j)
                    acc[i][j] = fmaf(a_[i], b_[j], acc[i][j]);
        }
        __syncthreads();
    }

    #pragma unroll
    for (int i = 0; i < 8; ++i) {
        const int o = tm * 8 + i;
        float* op = &out[(size_t)(b * C_ + o) * HW_ + hw0 + tn * 8];
        *(float4*)(op + 0) = make_float4(acc[i][0], acc[i][1], acc[i][2], acc[i][3]);
        *(float4*)(op + 4) = make_float4(acc[i][4], acc[i][5], acc[i][6], acc[i][7]);
    }
}

// ---------------------------------------------------------------------------
extern "C" void kernel_launch(void* const* d_in, const int* in_sizes, int n_in,
                              void* d_out, int out_size) {
    const float* x     = (const float*)d_in[0];  // (16,256,64,64)
    const float* dw    = (const float*)d_in[1];  // (256,1,31,31)
    const float* gamma = (const float*)d_in[2];  // (256,)
    const float* beta  = (const float*)d_in[3];  // (256,)
    const float* pw    = (const float*)d_in[4];  // (256,256)
    float* out = (float*)d_out;                  // (16,256,64,64)

    cudaFuncSetAttribute(dwconv_kernel,
                         cudaFuncAttributeMaxDynamicSharedMemorySize,
                         DW_SMEM_BYTES);

    transpose_kernel<<<dim3(8, 8), dim3(32, 8)>>>(pw);
    dwconv_kernel<<<NBLK, 128, DW_SMEM_BYTES>>>(x, dw);
    stats_kernel<<<1, C_>>>(gamma, beta);
    pw_kernel<<<dim3(HW_ / 64, B_), 256>>>(out);
}

// round 14
// speedup vs baseline: 1.1077x; 1.1077x over previous
#include <cuda_runtime.h>

#define B_  16
#define C_  256
#define H_  64
#define W_  64
#define K_  31
#define PAD_ 15
#define HW_ 4096

// dwconv: vertical-pair packed tile (R12-proven config, frozen)
#define PV_ROWS 62          // r = 0..61 ; pair (tile r, tile r+32)
#define PV_COLS 94          // 64 + 30 halo
#define PV_S    95          // f2 row stride (odd -> conflict-free LDS.64 across rows)
#define WROW    32          // padded weight row (f2 per kh); 16B-aligned rows
#define DW_SMEM_BYTES ((PV_ROWS * PV_S + K_ * WROW) * 8)

// Scratch (allocation-free rule: __device__ globals)
__device__ float g_y[(size_t)B_ * C_ * HW_];
__device__ float g_pwT[C_ * C_];              // pwT[c][o] = pw[o][c]
__device__ float g_psum[C_ * B_];
__device__ float g_psumsq[C_ * B_];
__device__ float g_scale[C_];
__device__ float g_bias[C_];

// Packed f32x2 FMA (Blackwell sm_103a; only reachable via PTX)
#define FMA2(d, a, b) \
    asm("fma.rn.f32x2 %0, %1, %2, %0;" : "+l"(d) : "l"(a), "l"(b))
#define PACK2(d, lo, hi) \
    asm("mov.b64 %0, {%1, %2};" : "=l"(d) : "f"(lo), "f"(hi))

union U2F { unsigned long long u; float2 f; };

// Bs mid-row gap mapping: word w -> w + 4*(w>=32)  (breaks 2-way bank conflict)
#define BS_COL(w) ((w) + (((w) >= 32) ? 4 : 0))

// ---------------------------------------------------------------------------
// Kernel 0: transpose pw (256x256) -> g_pwT
// ---------------------------------------------------------------------------
__global__ void transpose_kernel(const float* __restrict__ pw) {
    __shared__ float t[32][33];
    const int tx = threadIdx.x, ty = threadIdx.y;
    const int c0 = blockIdx.x * 32;
    const int o0 = blockIdx.y * 32;
    #pragma unroll
    for (int j = ty; j < 32; j += 8)
        t[j][tx] = pw[(o0 + j) * C_ + c0 + tx];
    __syncthreads();
    #pragma unroll
    for (int j = ty; j < 32; j += 8)
        g_pwT[(c0 + j) * C_ + o0 + tx] = t[tx][j];
}

// ---------------------------------------------------------------------------
// Kernel 1: depthwise 31x31 conv, vertical-pair FFMA2 (R12 exact, frozen).
// ---------------------------------------------------------------------------
__global__ void __launch_bounds__(128, 3)
dwconv_kernel(const float* __restrict__ x, const float* __restrict__ dw) {
    extern __shared__ float2 sm[];
    float2* pv   = sm;                       // pv[r*95+c] = (tile(r,c), tile(r+32,c))
    float2* wsm2 = sm + PV_ROWS * PV_S;      // duplicated weights (w,w), rows padded to 32
    __shared__ float red[2][4];

    const int bx  = blockIdx.x;
    const int c   = bx & (C_ - 1);
    const int b   = bx >> 8;
    const int tid = threadIdx.x;

    const float* wp = dw + c * (K_ * K_);
    for (int i = tid; i < K_ * K_; i += 128) {
        int kh = i / K_, kw = i - kh * K_;
        float w = wp[i];
        wsm2[kh * WROW + kw] = make_float2(w, w);
    }

    const float* xp = x + (size_t)(b * C_ + c) * HW_;
    for (int i = tid; i < PV_ROWS * PV_COLS; i += 128) {
        int r  = i / PV_COLS;
        int cc = i - r * PV_COLS;
        int gw = cc - PAD_;
        float v0 = 0.0f, v1 = 0.0f;
        if ((unsigned)gw < (unsigned)W_) {
            int gh0 = r - PAD_;
            int gh1 = r + 32 - PAD_;
            if ((unsigned)gh0 < (unsigned)H_) v0 = xp[gh0 * W_ + gw];
            if ((unsigned)gh1 < (unsigned)H_) v1 = xp[gh1 * W_ + gw];
        }
        pv[r * PV_S + cc] = make_float2(v0, v1);
    }
    __syncthreads();

    const int h  = tid & 31;
    const int w0 = (tid >> 5) << 4;

    unsigned long long acc2[16];
    #pragma unroll
    for (int j = 0; j < 16; ++j) acc2[j] = 0ULL;

    const unsigned long long* pvR =
        (const unsigned long long*)pv + (size_t)h * PV_S + w0;

    #pragma unroll 1
    for (int kh = 0; kh < K_; ++kh) {
        unsigned long long win[46];
        #pragma unroll
        for (int t = 0; t < 46; ++t) win[t] = pvR[t];

        const ulonglong2* wR2 = (const ulonglong2*)(wsm2 + kh * WROW);
        #pragma unroll
        for (int kwp = 0; kwp < 15; ++kwp) {
            ulonglong2 wq = wR2[kwp];
            #pragma unroll
            for (int j = 0; j < 16; ++j)
                FMA2(acc2[j], win[j + 2 * kwp], wq.x);
            #pragma unroll
            for (int j = 0; j < 16; ++j)
                FMA2(acc2[j], win[j + 2 * kwp + 1], wq.y);
        }
        {
            ulonglong2 wq = wR2[15];
            #pragma unroll
            for (int j = 0; j < 16; ++j)
                FMA2(acc2[j], win[j + 30], wq.x);
        }
        pvR += PV_S;
    }

    float* ypA = g_y + (size_t)(b * C_ + c) * HW_ + h * W_ + w0;
    float* ypB = ypA + 32 * W_;
    float s = 0.0f, s2 = 0.0f;
    float rowA[16], rowB[16];
    #pragma unroll
    for (int j = 0; j < 16; ++j) {
        U2F u; u.u = acc2[j];
        rowA[j] = u.f.x;
        rowB[j] = u.f.y;
        s  += u.f.x + u.f.y;
        s2  = fmaf(u.f.x, u.f.x, s2);
        s2  = fmaf(u.f.y, u.f.y, s2);
    }
    #pragma unroll
    for (int q = 0; q < 4; ++q) {
        *(float4*)(ypA + 4 * q) = make_float4(rowA[4*q], rowA[4*q+1], rowA[4*q+2], rowA[4*q+3]);
        *(float4*)(ypB + 4 * q) = make_float4(rowB[4*q], rowB[4*q+1], rowB[4*q+2], rowB[4*q+3]);
    }
    #pragma unroll
    for (int off = 16; off > 0; off >>= 1) {
        s  += __shfl_down_sync(0xffffffffu, s,  off);
        s2 += __shfl_down_sync(0xffffffffu, s2, off);
    }
    const int warp = tid >> 5;
    const int lane = tid & 31;
    if (lane == 0) { red[0][warp] = s; red[1][warp] = s2; }
    __syncthreads();
    if (tid == 0) {
        float ts = 0.0f, t2 = 0.0f;
        #pragma unroll
        for (int w = 0; w < 4; ++w) { ts += red[0][w]; t2 += red[1][w]; }
        g_psum[c * B_ + b]   = ts;
        g_psumsq[c * B_ + b] = t2;
    }
}

// ---------------------------------------------------------------------------
// Kernel 2: fold B partials per channel -> scale/bias  (deterministic)
// ---------------------------------------------------------------------------
__global__ void stats_kernel(const float* __restrict__ gamma,
                             const float* __restrict__ beta) {
    const int c = threadIdx.x;
    float s = 0.0f, s2 = 0.0f;
    #pragma unroll
    for (int b = 0; b < B_; ++b) {
        s  += g_psum[c * B_ + b];
        s2 += g_psumsq[c * B_ + b];
    }
    const float inv  = 1.0f / (float)(B_ * HW_);
    const float mean = s * inv;
    const float var  = s2 * inv - mean * mean;
    const float rstd = rsqrtf(var + 1e-5f);
    const float sc   = rstd * gamma[c];
    g_scale[c] = sc;
    g_bias[c]  = beta[c] - mean * sc;
}

// ---------------------------------------------------------------------------
// Kernel 3: fused normalize+ReLU+pointwise GEMM with FFMA2 inner loop.
// b-pairs come packed straight from Bs (ulonglong2 LDS.128, zero extra ops);
// a-duplicates built with 8 ALU movs per kk (ALU pipe is idle).
// Issue count per kk: 4 LDS.128 + 8 MOV + 32 FFMA2 = 44 (was 68).
// ---------------------------------------------------------------------------
__global__ void __launch_bounds__(256, 2)
pw_kernel(float* __restrict__ out) {
    __shared__ float As[16][256];
    __shared__ float Bs[16][68];    // gapped: word w at col w + 4*(w>=32)

    const int b   = blockIdx.y;
    const int hw0 = blockIdx.x * 64;
    const int tid = threadIdx.x;
    const int tm  = tid >> 3;          // 0..31 -> m block of 8
    const int tn  = tid & 7;           // 0..7  -> n block of 8
    const int lk  = tid >> 4;          // 0..15 (k row for loads)
    const int ln4 = (tid & 15) * 4;    // 0..60

    const int bsw    = BS_COL(ln4);
    const int bA_col = BS_COL(tn * 8);      // 16B-aligned (cols 0,8,16,24,36,44,52,60)
    const int bB_col = BS_COL(tn * 8 + 4);

    const float* yb = g_y + (size_t)b * C_ * HW_ + hw0;

    unsigned long long acc2[8][4];     // acc2[i][jp] = (out[i][2jp], out[i][2jp+1])
    #pragma unroll
    for (int i = 0; i < 8; ++i)
        #pragma unroll
        for (int jp = 0; jp < 4; ++jp) acc2[i][jp] = 0ULL;

    float4 a4[4], b4;
    #pragma unroll
    for (int p = 0; p < 4; ++p)
        a4[p] = *(const float4*)&g_pwT[lk * C_ + ln4 + 64 * p];
    b4 = *(const float4*)&yb[(size_t)lk * HW_ + ln4];

    for (int c0 = 0; c0 < C_; c0 += 16) {
        #pragma unroll
        for (int p = 0; p < 4; ++p)
            *(float4*)&As[lk][ln4 + 64 * p] = a4[p];
        {
            const int cc = c0 + lk;
            const float sc = g_scale[cc];
            const float bi = g_bias[cc];
            float4 r;
            r.x = fmaxf(fmaf(b4.x, sc, bi), 0.0f);
            r.y = fmaxf(fmaf(b4.y, sc, bi), 0.0f);
            r.z = fmaxf(fmaf(b4.z, sc, bi), 0.0f);
            r.w = fmaxf(fmaf(b4.w, sc, bi), 0.0f);
            *(float4*)&Bs[lk][bsw] = r;
        }
        __syncthreads();

        if (c0 + 16 < C_) {
            const int ck = c0 + 16 + lk;
            #pragma unroll
            for (int p = 0; p < 4; ++p)
                a4[p] = *(const float4*)&g_pwT[ck * C_ + ln4 + 64 * p];
            b4 = *(const float4*)&yb[(size_t)ck * HW_ + ln4];
        }

        #pragma unroll
        for (int kk = 0; kk < 16; ++kk) {
            float4 aA = *(const float4*)&As[kk][tm * 8];
            float4 aB = *(const float4*)&As[kk][tm * 8 + 4];
            // packed b pairs straight from shared (no movs)
            ulonglong2 bq0 = *(const ulonglong2*)&Bs[kk][bA_col]; // (b0,b1),(b2,b3)
            ulonglong2 bq1 = *(const ulonglong2*)&Bs[kk][bB_col]; // (b4,b5),(b6,b7)
            const unsigned long long bp[4] = {bq0.x, bq0.y, bq1.x, bq1.y};
            const float a_[8] = {aA.x, aA.y, aA.z, aA.w, aB.x, aB.y, aB.z, aB.w};
            #pragma unroll
            for (int i = 0; i < 8; ++i) {
                unsigned long long ad;
                PACK2(ad, a_[i], a_[i]);           // ALU mov, amortized over 4 FMA2
                #pragma unroll
                for (int jp = 0; jp < 4; ++jp)
                    FMA2(acc2[i][jp], bp[jp], ad);
            }
        }
        __syncthreads();
    }

    #pragma unroll
    for (int i = 0; i < 8; ++i) {
        const int o = tm * 8 + i;
        float* op = &out[(size_t)(b * C_ + o) * HW_ + hw0 + tn * 8];
        U2F u0, u1, u2, u3;
        u0.u = acc2[i][0]; u1.u = acc2[i][1];
        u2.u = acc2[i][2]; u3.u = acc2[i][3];
        *(float4*)(op + 0) = make_float4(u0.f.x, u0.f.y, u1.f.x, u1.f.y);
        *(float4*)(op + 4) = make_float4(u2.f.x, u2.f.y, u3.f.x, u3.f.y);
    }
}

// ---------------------------------------------------------------------------
extern "C" void kernel_launch(void* const* d_in, const int* in_sizes, int n_in,
                              void* d_out, int out_size) {
    const float* x     = (const float*)d_in[0];  // (16,256,64,64)
    const float* dw    = (const float*)d_in[1];  // (256,1,31,31)
    const float* gamma = (const float*)d_in[2];  // (256,)
    const float* beta  = (const float*)d_in[3];  // (256,)
    const float* pw    = (const float*)d_in[4];  // (256,256)
    float* out = (float*)d_out;                  // (16,256,64,64)

    cudaFuncSetAttribute(dwconv_kernel,
                         cudaFuncAttributeMaxDynamicSharedMemorySize,
                         DW_SMEM_BYTES);

    transpose_kernel<<<dim3(8, 8), dim3(32, 8)>>>(pw);
    dwconv_kernel<<<B_ * C_, 128, DW_SMEM_BYTES>>>(x, dw);
    stats_kernel<<<1, C_>>>(gamma, beta);
    pw_kernel<<<dim3(HW_ / 64, B_), 256>>>(out);
}